// round 4
// baseline (speedup 1.0000x reference)
#include <cuda_runtime.h>
#include <cstdint>

// Problem constants (fixed by the dataset)
#define H 4096
#define O 4096
#define E 8
#define B 8192

// GEMM tiling
#define BM 128
#define BN 128
#define BK 32
#define AST 36    // BM-tile A row stride (BK + 4 floats)  -> conflict-free A frags
#define BST 136   // BK-tile B row stride (BN + 8 floats)  -> conflict-free B frags
#define MT_PER_E ((B + BM - 1) / BM)   // 64 m-tiles per expert (worst case)

// ---------------- device scratch (static: no allocs allowed) ----------------
__device__ int           g_cnt[E];
__device__ int           g_tok[E * B];
__device__ float         g_wgt[E * B];
__device__ unsigned char g_slot[E * B];
__device__ float         g_scratch[(size_t)2 * B * O];   // per-slot outputs (256 MiB)

// ---------------- small helpers ----------------
__device__ __forceinline__ uint32_t f2tf(float f) {
    uint32_t r;
    asm("cvt.rna.tf32.f32 %0, %1;" : "=r"(r) : "f"(f));
    return r;
}

__device__ __forceinline__ void cp16(float* dst, const float* src, int src_bytes) {
    uint32_t d = (uint32_t)__cvta_generic_to_shared(dst);
    asm volatile("cp.async.cg.shared.global [%0], [%1], 16, %2;"
                 :: "r"(d), "l"(src), "r"(src_bytes));
}
__device__ __forceinline__ void cp_commit() {
    asm volatile("cp.async.commit_group;");
}
template <int N>
__device__ __forceinline__ void cp_wait() {
    asm volatile("cp.async.wait_group %0;" :: "n"(N));
}

// ---------------- kernel 0: reset routing counters (graph-replay safe) ------
__global__ void zero_cnt_kernel() {
    if (threadIdx.x < E) g_cnt[threadIdx.x] = 0;
}

// ---------------- kernel 1: gating (logits -> top2 -> softmax -> lists) -----
__global__ void gate_kernel(const float* __restrict__ x,
                            const float* __restrict__ gw) {
    const int b   = blockIdx.x;
    const int tid = threadIdx.x;   // 128 threads
    const float* xr = x + (size_t)b * H;

    float s0=0.f,s1=0.f,s2=0.f,s3=0.f,s4=0.f,s5=0.f,s6=0.f,s7=0.f;
    for (int h = tid; h < H; h += 128) {
        float xv = xr[h];
        const float4* g = reinterpret_cast<const float4*>(gw + (size_t)h * E);
        float4 ga = g[0], gb = g[1];
        s0 += xv * ga.x; s1 += xv * ga.y; s2 += xv * ga.z; s3 += xv * ga.w;
        s4 += xv * gb.x; s5 += xv * gb.y; s6 += xv * gb.z; s7 += xv * gb.w;
    }

    __shared__ float red[E][128];
    red[0][tid]=s0; red[1][tid]=s1; red[2][tid]=s2; red[3][tid]=s3;
    red[4][tid]=s4; red[5][tid]=s5; red[6][tid]=s6; red[7][tid]=s7;
    __syncthreads();
    for (int off = 64; off > 0; off >>= 1) {
        if (tid < off) {
            #pragma unroll
            for (int e = 0; e < E; ++e) red[e][tid] += red[e][tid + off];
        }
        __syncthreads();
    }

    if (tid == 0) {
        float l[E];
        #pragma unroll
        for (int e = 0; e < E; ++e) l[e] = red[e][0];
        // top-2 with jax tie-breaking (lowest index wins via strict >)
        int e0 = 0; float v0 = l[0];
        #pragma unroll
        for (int e = 1; e < E; ++e) if (l[e] > v0) { v0 = l[e]; e0 = e; }
        int e1 = -1; float v1 = -3.4e38f;
        #pragma unroll
        for (int e = 0; e < E; ++e) if (e != e0 && l[e] > v1) { v1 = l[e]; e1 = e; }
        // softmax over [v0, v1] (v0 >= v1)
        float ex  = expf(v1 - v0);
        float inv = 1.0f / (1.0f + ex);
        float w0 = inv, w1 = ex * inv;

        int p0 = atomicAdd(&g_cnt[e0], 1);
        g_tok[e0 * B + p0] = b; g_wgt[e0 * B + p0] = w0; g_slot[e0 * B + p0] = 0;
        int p1 = atomicAdd(&g_cnt[e1], 1);
        g_tok[e1 * B + p1] = b; g_wgt[e1 * B + p1] = w1; g_slot[e1 * B + p1] = 1;
    }
}

// ---------------- kernel 2: gathered expert GEMM (tf32 mma.sync) ------------
__global__ __launch_bounds__(256, 2)
void moe_gemm_kernel(const float* __restrict__ x, const float* __restrict__ ew) {
    const int e   = blockIdx.y >> 6;          // 64 m-tiles per expert
    const int mt  = blockIdx.y & 63;
    const int cnt = g_cnt[e];
    const int row0 = mt * BM;
    if (row0 >= cnt) return;                  // empty tile -> exit
    const int n0 = blockIdx.x * BN;
    const float* W = ew + (size_t)e * H * O;

    extern __shared__ float smem[];
    float* As = smem;                   // [2][BM][AST]
    float* Bs = smem + 2 * BM * AST;    // [2][BK][BST]

    __shared__ int   s_tok[BM];
    __shared__ float s_w[BM];
    __shared__ int   s_slot[BM];

    const int tid = threadIdx.x;        // 256 threads
    if (tid < BM) {
        int r = row0 + tid;
        if (r < cnt) {
            s_tok[tid]  = g_tok[e * B + r];
            s_w[tid]    = g_wgt[e * B + r];
            s_slot[tid] = g_slot[e * B + r];
        } else {
            s_tok[tid] = -1; s_w[tid] = 0.f; s_slot[tid] = 0;
        }
    }
    __syncthreads();

    auto load_stage = [&](int buf, int k0) {
        float* Ab = As + buf * BM * AST;
        float* Bb = Bs + buf * BK * BST;
        #pragma unroll
        for (int j = 0; j < 4; ++j) {                 // A: 128 rows x 32 k
            int lin = tid + j * 256;
            int m = lin >> 3, kq = lin & 7;
            int tok = s_tok[m];
            const float* src = x + (size_t)(tok < 0 ? 0 : tok) * H + k0 + kq * 4;
            cp16(Ab + m * AST + kq * 4, src, tok < 0 ? 0 : 16);  // zfill padding rows
        }
        #pragma unroll
        for (int j = 0; j < 4; ++j) {                 // B: 32 k x 128 n
            int lin = tid + j * 256;
            int k = lin >> 5, nq = lin & 31;
            cp16(Bb + k * BST + nq * 4, W + (size_t)(k0 + k) * O + n0 + nq * 4, 16);
        }
    };

    float acc[4][4][4];
    #pragma unroll
    for (int i = 0; i < 4; ++i)
        #pragma unroll
        for (int j = 0; j < 4; ++j)
            #pragma unroll
            for (int r = 0; r < 4; ++r) acc[i][j][r] = 0.f;

    const int wid = tid >> 5, lane = tid & 31;
    const int wm = wid >> 2, wn = wid & 3;        // 2 (m) x 4 (n) warps
    const int gi = lane >> 2, qi = lane & 3;

    load_stage(0, 0); cp_commit();
    int buf = 0;
    const int KT = H / BK;                        // 128
    for (int kt = 0; kt < KT; ++kt) {
        if (kt + 1 < KT) { load_stage(buf ^ 1, (kt + 1) * BK); cp_commit(); cp_wait<1>(); }
        else             { cp_wait<0>(); }
        __syncthreads();

        const float* Ab = As + buf * BM * AST;
        const float* Bb = Bs + buf * BK * BST;
        #pragma unroll
        for (int kk = 0; kk < BK; kk += 8) {
            uint32_t a[4][4];
            #pragma unroll
            for (int mi = 0; mi < 4; ++mi) {
                int rb = wm * 64 + mi * 16 + gi;
                a[mi][0] = f2tf(Ab[(rb    ) * AST + kk + qi    ]);
                a[mi][1] = f2tf(Ab[(rb + 8) * AST + kk + qi    ]);
                a[mi][2] = f2tf(Ab[(rb    ) * AST + kk + qi + 4]);
                a[mi][3] = f2tf(Ab[(rb + 8) * AST + kk + qi + 4]);
            }
            uint32_t bfr[4][2];
            #pragma unroll
            for (int ni = 0; ni < 4; ++ni) {
                int nb = wn * 32 + ni * 8 + gi;
                bfr[ni][0] = f2tf(Bb[(kk + qi    ) * BST + nb]);
                bfr[ni][1] = f2tf(Bb[(kk + qi + 4) * BST + nb]);
            }
            #pragma unroll
            for (int mi = 0; mi < 4; ++mi)
                #pragma unroll
                for (int ni = 0; ni < 4; ++ni)
                    asm volatile(
                        "mma.sync.aligned.m16n8k8.row.col.f32.tf32.tf32.f32 "
                        "{%0,%1,%2,%3}, {%4,%5,%6,%7}, {%8,%9}, {%0,%1,%2,%3};"
                        : "+f"(acc[mi][ni][0]), "+f"(acc[mi][ni][1]),
                          "+f"(acc[mi][ni][2]), "+f"(acc[mi][ni][3])
                        : "r"(a[mi][0]), "r"(a[mi][1]), "r"(a[mi][2]), "r"(a[mi][3]),
                          "r"(bfr[ni][0]), "r"(bfr[ni][1]));
        }
        __syncthreads();
        buf ^= 1;
    }

    // Epilogue: scale by gate weight, store to per-slot scratch (no atomics).
    #pragma unroll
    for (int mi = 0; mi < 4; ++mi) {
        #pragma unroll
        for (int half = 0; half < 2; ++half) {
            int rl  = wm * 64 + mi * 16 + gi + half * 8;
            int tok = s_tok[rl];
            if (tok < 0) continue;
            float w = s_w[rl];
            float* base = g_scratch + ((size_t)s_slot[rl] * B + tok) * O + n0 + wn * 32;
            #pragma unroll
            for (int ni = 0; ni < 4; ++ni) {
                float2 v;
                v.x = w * acc[mi][ni][half * 2];
                v.y = w * acc[mi][ni][half * 2 + 1];
                *reinterpret_cast<float2*>(base + ni * 8 + qi * 2) = v;
            }
        }
    }
}

// ---------------- kernel 3: combine slots -> out -----------------------------
__global__ void combine_kernel(float* __restrict__ out) {
    size_t i = (size_t)blockIdx.x * blockDim.x + threadIdx.x;   // float4 index
    const float4* sA = reinterpret_cast<const float4*>(g_scratch);
    const float4* sB = reinterpret_cast<const float4*>(g_scratch + (size_t)B * O);
    float4 a = sA[i], b = sB[i];
    float4 r;
    r.x = a.x + b.x; r.y = a.y + b.y; r.z = a.z + b.z; r.w = a.w + b.w;
    reinterpret_cast<float4*>(out)[i] = r;
}

// ---------------- launch ----------------
extern "C" void kernel_launch(void* const* d_in, const int* in_sizes, int n_in,
                              void* d_out, int out_size) {
    const float* x  = (const float*)d_in[0];   // [B, 1, H]
    const float* gw = (const float*)d_in[1];   // [H, E]
    const float* ew = (const float*)d_in[2];   // [E, H, O]
    float* out = (float*)d_out;                // [B, 1, O] fp32

    const int smem_bytes = (2 * BM * AST + 2 * BK * BST) * (int)sizeof(float); // 71680
    cudaFuncSetAttribute(moe_gemm_kernel,
                         cudaFuncAttributeMaxDynamicSharedMemorySize, smem_bytes);

    zero_cnt_kernel<<<1, 32>>>();
    gate_kernel<<<B, 128>>>(x, gw);
    moe_gemm_kernel<<<dim3(O / BN, E * MT_PER_E), 256, smem_bytes>>>(x, ew);
    combine_kernel<<<(unsigned)(((size_t)B * O / 4) / 256), 256>>>(out);
}